// round 1
// baseline (speedup 1.0000x reference)
#include <cuda_runtime.h>
#include <math.h>

#define NN 8192
#define DD 64
#define NSPLIT 8
#define TJ 128
#define JCHUNK (NN / NSPLIT)

// ---- static device scratch (no allocation allowed) ----
__device__ float g_G[NN * DD];                 // 2 MB  : G = relu(X@W+b)@wt
__device__ float g_V[NN * DD];                 // 2 MB  : layer output
__device__ float g_num[NSPLIT * NN * DD];      // 16 MB : partial numerators
__device__ float g_den[NSPLIT * NN];           // partial denominators
__device__ float g_part[64 * 64];              // row-sum partials

// ============================================================
// prep: G = relu(X @ W + b) @ wt      (X: N x din, W: din x 64, wt: 64 x 64)
// 256 threads = 4 groups of 64; each group handles one row; 32 rows/block.
// ============================================================
__global__ __launch_bounds__(256) void prep_kernel(
    const float* __restrict__ Xext, int din,
    const float* __restrict__ W, const float* __restrict__ b,
    const float* __restrict__ wt)
{
    __shared__ float sW[64 * 64];
    __shared__ float swt[64 * 64];
    __shared__ float sx[4][64];
    __shared__ float sh[4][64];

    const float* X = Xext ? Xext : g_V;
    int tid = threadIdx.x;
    int g = tid >> 6;
    int k = tid & 63;

    for (int t = tid; t < din * 64; t += 256) sW[t] = W[t];
    for (int t = tid; t < 64 * 64; t += 256) swt[t] = wt[t];
    float bk = b[k];
    __syncthreads();

    int rowbase = blockIdx.x * 32;
    for (int rb = 0; rb < 8; rb++) {
        int row = rowbase + rb * 4 + g;
        if (k < din) sx[g][k] = X[row * din + k];
        __syncthreads();
        float h = bk;
        for (int d = 0; d < din; d++) h += sx[g][d] * sW[d * 64 + k];
        h = fmaxf(h, 0.f);
        sh[g][k] = h;
        __syncthreads();
        float acc = 0.f;
        #pragma unroll 8
        for (int m = 0; m < 64; m++) acc += sh[g][m] * swt[m * 64 + k];
        g_G[row * 64 + k] = acc;
        __syncthreads();
    }
}

// ============================================================
// pass: fused attention-like S@G. Weights w_ij = exp(exp(-alpha*dR2_ij))
// recomputed on the fly (no O(N^2) memory). One row per thread.
// Each block covers (256 rows) x (JCHUNK j's); partials written to scratch.
// ============================================================
__global__ __launch_bounds__(256, 2) void pass_kernel(
    const float* __restrict__ x, const float* __restrict__ alpha)
{
    __shared__ float sG[TJ][DD];   // 32 KB
    __shared__ float sEta[TJ];
    __shared__ float sPhi[TJ];

    const float PI_F    = 3.14159265358979323846f;
    const float TWOPI_F = 6.28318530717958647692f;

    int tid = threadIdx.x;
    int row = blockIdx.x * 256 + tid;
    int jsplit = blockIdx.y;
    int j0 = jsplit * JCHUNK;

    float a = alpha[0];
    float eta_i = x[row * 7 + 1];
    float phi_i = x[row * 7 + 2];

    unsigned long long acc[DD / 2];
    #pragma unroll
    for (int k = 0; k < DD / 2; k++) acc[k] = 0ULL;
    float dacc = 0.f;

    for (int jt = 0; jt < JCHUNK; jt += TJ) {
        __syncthreads();
        int base = j0 + jt;
        // load tile of G: TJ*DD floats = 2048 float4, 8 per thread
        const float4* Gsrc = (const float4*)(g_G + base * DD);
        float4* Gdst = (float4*)&sG[0][0];
        #pragma unroll
        for (int t = 0; t < (TJ * DD / 4) / 256; t++)
            Gdst[tid + t * 256] = Gsrc[tid + t * 256];
        if (tid < TJ) {
            sEta[tid] = x[(base + tid) * 7 + 1];
            sPhi[tid] = x[(base + tid) * 7 + 2];
        }
        __syncthreads();

        for (int jj = 0; jj < TJ; jj++) {
            float de = eta_i - sEta[jj];
            float dp = fabsf(phi_i - sPhi[jj]);
            // where(dp > pi, 2pi - dp, dp) == fmin(dp, 2pi - dp) (squared after)
            dp = fminf(dp, TWOPI_F - dp);
            float dr = de * de + dp * dp;
            float w = __expf(__expf(-a * dr));
            dacc += w;
            unsigned long long ww;
            asm("mov.b64 %0, {%1, %1};" : "=l"(ww) : "r"(__float_as_uint(w)));
            const ulonglong2* gj = (const ulonglong2*)&sG[jj][0];
            #pragma unroll
            for (int k = 0; k < DD / 4; k++) {
                ulonglong2 gv = gj[k];
                asm("fma.rn.f32x2 %0, %1, %2, %0;" : "+l"(acc[2 * k + 0]) : "l"(ww), "l"(gv.x));
                asm("fma.rn.f32x2 %0, %1, %2, %0;" : "+l"(acc[2 * k + 1]) : "l"(ww), "l"(gv.y));
            }
        }
    }

    float2* nout = (float2*)(g_num + (size_t)jsplit * NN * DD + (size_t)row * DD);
    #pragma unroll
    for (int k = 0; k < DD / 2; k++) {
        unsigned int lo = (unsigned int)(acc[k] & 0xffffffffULL);
        unsigned int hi = (unsigned int)(acc[k] >> 32);
        nout[k] = make_float2(__uint_as_float(lo), __uint_as_float(hi));
    }
    g_den[jsplit * NN + row] = dacc;
}

// ============================================================
// finalize: V = relu(num/den + G + bs)
// ============================================================
__global__ __launch_bounds__(256) void finalize_kernel(const float* __restrict__ bs)
{
    int gid = blockIdx.x * 256 + threadIdx.x;   // over NN*DD
    int i = gid >> 6;
    float ds = 0.f;
    #pragma unroll
    for (int s = 0; s < NSPLIT; s++) ds += g_den[s * NN + i];
    float ns = 0.f;
    #pragma unroll
    for (int s = 0; s < NSPLIT; s++) ns += g_num[(size_t)s * NN * DD + gid];
    float v = ns / ds + g_G[gid] + bs[0];
    g_V[gid] = fmaxf(v, 0.f);
}

// ============================================================
// reduce: column sums of V over 128-row slabs -> g_part[64][64]
// ============================================================
__global__ __launch_bounds__(256) void reduce_kernel()
{
    __shared__ float s[4][64];
    int tid = threadIdx.x;
    int k = tid & 63;
    int rg = tid >> 6;
    int b = blockIdx.x;   // 64 blocks, 128 rows each
    float acc = 0.f;
    for (int r = rg; r < 128; r += 4)
        acc += g_V[(b * 128 + r) * 64 + k];
    s[rg][k] = acc;
    __syncthreads();
    if (tid < 64)
        g_part[b * 64 + tid] = s[0][tid] + s[1][tid] + s[2][tid] + s[3][tid];
}

// ============================================================
// head: s = total column sums; out = sigmoid(s . Wl + bl)
// ============================================================
__global__ void head_kernel(const float* __restrict__ Wl,
                            const float* __restrict__ bl,
                            float* __restrict__ out)
{
    __shared__ float sv[64];
    int t = threadIdx.x;   // 64 threads
    float sk = 0.f;
    for (int b = 0; b < 64; b++) sk += g_part[b * 64 + t];
    sv[t] = sk * Wl[t];
    __syncthreads();
    if (t == 0) {
        float s = 0.f;
        for (int i = 0; i < 64; i++) s += sv[i];
        s += bl[0];
        out[0] = 1.f / (1.f + expf(-s));
    }
}

extern "C" void kernel_launch(void* const* d_in, const int* in_sizes, int n_in,
                              void* d_out, int out_size)
{
    const float* x     = (const float*)d_in[0];
    const float* alpha = (const float*)d_in[1];
    const float* W1    = (const float*)d_in[2];
    const float* b1    = (const float*)d_in[3];
    const float* wt1   = (const float*)d_in[4];
    const float* bs1   = (const float*)d_in[5];
    const float* W2    = (const float*)d_in[6];
    const float* b2    = (const float*)d_in[7];
    const float* wt2   = (const float*)d_in[8];
    const float* bs2   = (const float*)d_in[9];
    const float* Wl    = (const float*)d_in[10];
    const float* bl    = (const float*)d_in[11];
    float* out = (float*)d_out;

    dim3 pg(NN / 256, NSPLIT);

    // layer 1
    prep_kernel<<<NN / 32, 256>>>(x, 7, W1, b1, wt1);
    pass_kernel<<<pg, 256>>>(x, alpha);
    finalize_kernel<<<NN * DD / 256, 256>>>(bs1);
    // layer 2
    prep_kernel<<<NN / 32, 256>>>(nullptr, 64, W2, b2, wt2);
    pass_kernel<<<pg, 256>>>(x, alpha);
    finalize_kernel<<<NN * DD / 256, 256>>>(bs2);
    // head
    reduce_kernel<<<64, 256>>>();
    head_kernel<<<1, 64>>>(Wl, bl, out);
}

// round 3
// speedup vs baseline: 4.2313x; 4.2313x over previous
#include <cuda_runtime.h>
#include <cuda_fp16.h>
#include <math.h>
#include <stdint.h>

#define NN 8192
#define DD 64
#define NSPLIT 2
#define MT 128          // rows per CTA
#define JT 128          // j tile
#define NTILE (NN / NSPLIT / JT)   // 32 j-tiles per CTA
#define SGS 136         // padded sG row stride (halves)

// ---- static device scratch (no allocation allowed) ----
__device__ float  g_G[NN * DD];            // G = relu(X@W+b)@wt (fp32, row-major)
__device__ __half g_GT[DD * NN];           // G transposed, fp16 (feature-major)
__device__ float  g_V[NN * DD];            // layer output
__device__ float  g_num[NSPLIT * NN * DD]; // numerator partials
__device__ float  g_den[NSPLIT * NN];      // denominator partials
__device__ float2 g_ep[NN];                // packed (eta, phi)
__device__ float  g_part[64 * 64];

// ============================================================
// ep: pack (eta, phi) contiguously
// ============================================================
__global__ void ep_kernel(const float* __restrict__ x) {
    int j = blockIdx.x * 256 + threadIdx.x;
    g_ep[j] = make_float2(x[j * 7 + 1], x[j * 7 + 2]);
}

// ============================================================
// prep: G = relu(X@W+b)@wt with W/wt columns in registers.
// Writes g_G (fp32 row-major) and g_GT (fp16 transposed).
// ============================================================
template<int DIN>
__global__ __launch_bounds__(256) void prep_kernel(
    const float* __restrict__ Xext, const float* __restrict__ W,
    const float* __restrict__ b, const float* __restrict__ wt)
{
    __shared__ float sx[4][(DIN <= 8) ? 8 : 64];
    __shared__ float sh[4][64];
    __shared__ __half sgt[32][64];

    const int tid = threadIdx.x;
    const int g = tid >> 6, k = tid & 63;

    float Wreg[DIN], wtreg[64];
    #pragma unroll
    for (int d = 0; d < DIN; d++) Wreg[d] = W[d * 64 + k];
    #pragma unroll
    for (int m = 0; m < 64; m++) wtreg[m] = wt[m * 64 + k];
    const float bk = b[k];
    const float* X = Xext ? Xext : g_V;
    const int rowbase = blockIdx.x * 32;

    for (int rb = 0; rb < 8; rb++) {
        int row = rowbase + rb * 4 + g;
        if (k < DIN) sx[g][k] = X[row * DIN + k];
        __syncthreads();
        float h = bk;
        #pragma unroll
        for (int d = 0; d < DIN; d++) h = fmaf(sx[g][d], Wreg[d], h);
        h = fmaxf(h, 0.f);
        sh[g][k] = h;
        __syncthreads();
        float acc = 0.f;
        #pragma unroll
        for (int m = 0; m < 64; m++) acc = fmaf(sh[g][m], wtreg[m], acc);
        g_G[row * 64 + k] = acc;
        sgt[rb * 4 + g][k] = __float2half(acc);
    }
    __syncthreads();
    // coalesced transposed store: g_GT[k][rowbase..rowbase+31]
    const int kk = tid >> 2, seg = tid & 3;
    __half tmp[8];
    #pragma unroll
    for (int r = 0; r < 8; r++) tmp[r] = sgt[seg * 8 + r][kk];
    *(float4*)(g_GT + kk * NN + rowbase + seg * 8) = *(float4*)tmp;
}

// ============================================================
// weight: w = exp(exp(-alpha*dR2)) via two ex2.approx
// ============================================================
__device__ __forceinline__ float wfun(float ei, float pii, float ex, float px, float c1) {
    const float TWOPI = 6.28318530717958647692f;
    const float LOG2E = 1.44269504088896340736f;
    float de = ei - ex;
    float dp = fabsf(pii - px);
    dp = fminf(dp, TWOPI - dp);
    float dr = fmaf(de, de, dp * dp);
    float u; asm("ex2.approx.f32 %0, %1;" : "=f"(u) : "f"(c1 * dr));
    float w; asm("ex2.approx.f32 %0, %1;" : "=f"(w) : "f"(u * LOG2E));
    return w;
}

__device__ __forceinline__ uint32_t packh2(float a, float b) {
    __half2 h = __floats2half2_rn(a, b);
    return *(uint32_t*)&h;
}

// ============================================================
// pass: S@G on HMMA (mma.sync m16n8k16). A-fragment (weights) generated
// in registers on the fly; B = G^T tile via ldmatrix; fp32 denominator.
// ============================================================
__global__ __launch_bounds__(256, 1) void pass_kernel(const float* __restrict__ alpha)
{
    __shared__ __half sG[64 * SGS];   // [feature][j] padded
    __shared__ float2 sEP[JT];

    const int tid = threadIdx.x;
    const int warp = tid >> 5, lane = tid & 31;
    const int gid = lane >> 2, tig = lane & 3;
    const int rowtile = blockIdx.x, jsplit = blockIdx.y;
    const int j0base = jsplit * (NN / NSPLIT);

    const float LOG2E = 1.44269504088896340736f;
    const float c1 = -alpha[0] * LOG2E;

    const int row0 = rowtile * MT + warp * 16 + gid;
    const float2 e0 = g_ep[row0];
    const float2 e1 = g_ep[row0 + 8];

    // ldmatrix per-lane address offset (halves): matrices (nt,kh) pairs
    const int m = lane >> 3;
    const int bro = ((m >> 1) * 8 + (lane & 7)) * SGS + (m & 1) * 8;

    uint32_t sgb;
    asm("{ .reg .u64 t; cvta.to.shared.u64 t, %1; cvt.u32.u64 %0, t; }" : "=r"(sgb) : "l"(sG));

    float acc[8][4];
    #pragma unroll
    for (int nt = 0; nt < 8; nt++)
        #pragma unroll
        for (int q = 0; q < 4; q++) acc[nt][q] = 0.f;
    float d0 = 0.f, d1 = 0.f;

    for (int t = 0; t < NTILE; t++) {
        const int j0 = j0base + t * JT;
        __syncthreads();
        // load G tile: 64 x 128 halves
        #pragma unroll
        for (int i = 0; i < 4; i++) {
            int idx = tid + i * 256;
            int f = idx >> 4, c = idx & 15;
            *(float4*)(sG + f * SGS + c * 8) = *(const float4*)(g_GT + f * NN + j0 + c * 8);
        }
        if (tid < 64)
            ((float4*)sEP)[tid] = ((const float4*)((const float*)g_ep + j0 * 2))[tid];
        __syncthreads();

        #pragma unroll
        for (int ks = 0; ks < 8; ks++) {
            const int jj = ks * 16;
            // ---- A fragment: 8 weights in mma layout ----
            float4 p0 = *(const float4*)(&sEP[jj + tig * 2]);       // k-half 0: j, j+1
            float4 p1 = *(const float4*)(&sEP[jj + 8 + tig * 2]);   // k-half 1
            float w00 = wfun(e0.x, e0.y, p0.x, p0.y, c1);
            float w01 = wfun(e0.x, e0.y, p0.z, p0.w, c1);
            float w10 = wfun(e1.x, e1.y, p0.x, p0.y, c1);
            float w11 = wfun(e1.x, e1.y, p0.z, p0.w, c1);
            float w02 = wfun(e0.x, e0.y, p1.x, p1.y, c1);
            float w03 = wfun(e0.x, e0.y, p1.z, p1.w, c1);
            float w12 = wfun(e1.x, e1.y, p1.x, p1.y, c1);
            float w13 = wfun(e1.x, e1.y, p1.z, p1.w, c1);
            d0 += (w00 + w01) + (w02 + w03);
            d1 += (w10 + w11) + (w12 + w13);
            uint32_t af0 = packh2(w00, w01);
            uint32_t af1 = packh2(w10, w11);
            uint32_t af2 = packh2(w02, w03);
            uint32_t af3 = packh2(w12, w13);

            // ---- B fragments via ldmatrix.x4 (2 n-tiles each) ----
            uint32_t bf[8][2];
            #pragma unroll
            for (int q = 0; q < 4; q++) {
                uint32_t addr = sgb + (uint32_t)(q * 16 * SGS + bro + jj) * 2u;
                asm volatile("ldmatrix.sync.aligned.m8n8.x4.shared.b16 {%0,%1,%2,%3}, [%4];"
                    : "=r"(bf[2 * q][0]), "=r"(bf[2 * q][1]),
                      "=r"(bf[2 * q + 1][0]), "=r"(bf[2 * q + 1][1])
                    : "r"(addr));
            }
            // ---- MMAs ----
            #pragma unroll
            for (int nt = 0; nt < 8; nt++) {
                asm volatile(
                    "mma.sync.aligned.m16n8k16.row.col.f32.f16.f16.f32 "
                    "{%0,%1,%2,%3}, {%4,%5,%6,%7}, {%8,%9}, {%0,%1,%2,%3};"
                    : "+f"(acc[nt][0]), "+f"(acc[nt][1]), "+f"(acc[nt][2]), "+f"(acc[nt][3])
                    : "r"(af0), "r"(af1), "r"(af2), "r"(af3),
                      "r"(bf[nt][0]), "r"(bf[nt][1]));
            }
        }
    }

    // denominator: reduce over the 4 lanes of the tig group
    d0 += __shfl_xor_sync(0xffffffffu, d0, 1);
    d0 += __shfl_xor_sync(0xffffffffu, d0, 2);
    d1 += __shfl_xor_sync(0xffffffffu, d1, 1);
    d1 += __shfl_xor_sync(0xffffffffu, d1, 2);

    float* np = g_num + (size_t)jsplit * NN * DD;
    #pragma unroll
    for (int nt = 0; nt < 8; nt++) {
        *(float2*)(np + (size_t)row0 * DD + nt * 8 + tig * 2) =
            make_float2(acc[nt][0], acc[nt][1]);
        *(float2*)(np + (size_t)(row0 + 8) * DD + nt * 8 + tig * 2) =
            make_float2(acc[nt][2], acc[nt][3]);
    }
    if (tig == 0) {
        g_den[jsplit * NN + row0] = d0;
        g_den[jsplit * NN + row0 + 8] = d1;
    }
}

// ============================================================
// finalize: V = relu(num/den + G + bs)
// ============================================================
__global__ __launch_bounds__(256) void finalize_kernel(const float* __restrict__ bs)
{
    int gid = blockIdx.x * 256 + threadIdx.x;
    int i = gid >> 6;
    float ds = g_den[i] + g_den[NN + i];
    float ns = g_num[gid] + g_num[NN * DD + gid];
    float v = ns / ds + g_G[gid] + bs[0];
    g_V[gid] = fmaxf(v, 0.f);
}

// ============================================================
// reduce + head
// ============================================================
__global__ __launch_bounds__(256) void reduce_kernel()
{
    __shared__ float s[4][64];
    int tid = threadIdx.x;
    int k = tid & 63;
    int rg = tid >> 6;
    int bkt = blockIdx.x;
    float acc = 0.f;
    for (int r = rg; r < 128; r += 4)
        acc += g_V[(bkt * 128 + r) * 64 + k];
    s[rg][k] = acc;
    __syncthreads();
    if (tid < 64)
        g_part[bkt * 64 + tid] = s[0][tid] + s[1][tid] + s[2][tid] + s[3][tid];
}

__global__ void head_kernel(const float* __restrict__ Wl,
                            const float* __restrict__ bl,
                            float* __restrict__ out)
{
    __shared__ float sv[64];
    int t = threadIdx.x;
    float sk = 0.f;
    for (int b = 0; b < 64; b++) sk += g_part[b * 64 + t];
    sv[t] = sk * Wl[t];
    __syncthreads();
    if (t == 0) {
        float s = 0.f;
        for (int i = 0; i < 64; i++) s += sv[i];
        s += bl[0];
        out[0] = 1.f / (1.f + expf(-s));
    }
}

extern "C" void kernel_launch(void* const* d_in, const int* in_sizes, int n_in,
                              void* d_out, int out_size)
{
    const float* x     = (const float*)d_in[0];
    const float* alpha = (const float*)d_in[1];
    const float* W1    = (const float*)d_in[2];
    const float* b1    = (const float*)d_in[3];
    const float* wt1   = (const float*)d_in[4];
    const float* bs1   = (const float*)d_in[5];
    const float* W2    = (const float*)d_in[6];
    const float* b2    = (const float*)d_in[7];
    const float* wt2   = (const float*)d_in[8];
    const float* bs2   = (const float*)d_in[9];
    const float* Wl    = (const float*)d_in[10];
    const float* bl    = (const float*)d_in[11];
    float* out = (float*)d_out;

    dim3 pg(NN / MT, NSPLIT);

    ep_kernel<<<NN / 256, 256>>>(x);
    // layer 1
    prep_kernel<7><<<NN / 32, 256>>>(x, W1, b1, wt1);
    pass_kernel<<<pg, 256>>>(alpha);
    finalize_kernel<<<NN * DD / 256, 256>>>(bs1);
    // layer 2
    prep_kernel<64><<<NN / 32, 256>>>(nullptr, W2, b2, wt2);
    pass_kernel<<<pg, 256>>>(alpha);
    finalize_kernel<<<NN * DD / 256, 256>>>(bs2);
    // head
    reduce_kernel<<<64, 256>>>();
    head_kernel<<<1, 64>>>(Wl, bl, out);
}

// round 4
// speedup vs baseline: 4.6272x; 1.0936x over previous
#include <cuda_runtime.h>
#include <cuda_fp16.h>
#include <math.h>
#include <stdint.h>

#define NN 8192
#define DD 64
#define NSPLIT 4
#define MT 128          // rows per CTA
#define JT 128          // j tile
#define JSPAN (NN / NSPLIT)        // 2048 j's per CTA
#define NTILE (JSPAN / JT)         // 16 j-tiles per CTA
#define SGS 136         // padded sG row stride (halves)

// ---- static device scratch (no allocation allowed) ----
__device__ float  g_G[NN * DD];            // G = relu(X@W+b)@wt (fp32, row-major)
__device__ __half g_GT[DD * NN];           // G transposed, fp16 (feature-major)
__device__ float  g_V[NN * DD];            // layer output
__device__ float  g_num[NSPLIT * NN * DD]; // numerator partials
__device__ float  g_den[NSPLIT * NN];      // denominator partials
__device__ float2 g_ep[NN];                // scaled (eta*s, phi*s)
__device__ float  g_part[64 * 64];

// ============================================================
// ep: pack (eta, phi), pre-scaled by s = sqrt(alpha * log2(e))
// so that  2^(-(de^2+dp^2))  ==  exp(-alpha * dR^2)
// ============================================================
__global__ void ep_kernel(const float* __restrict__ x, const float* __restrict__ alpha) {
    const float LOG2E = 1.44269504088896340736f;
    float s = sqrtf(alpha[0] * LOG2E);
    int j = blockIdx.x * 256 + threadIdx.x;
    g_ep[j] = make_float2(x[j * 7 + 1] * s, x[j * 7 + 2] * s);
}

// ============================================================
// prep: G = relu(X@W+b)@wt with W/wt columns in registers.
// Writes g_G (fp32 row-major) and g_GT (fp16 transposed).
// ============================================================
template<int DIN>
__global__ __launch_bounds__(256) void prep_kernel(
    const float* __restrict__ Xext, const float* __restrict__ W,
    const float* __restrict__ b, const float* __restrict__ wt)
{
    __shared__ float sx[4][(DIN <= 8) ? 8 : 64];
    __shared__ float sh[4][64];
    __shared__ __half sgt[32][64];

    const int tid = threadIdx.x;
    const int g = tid >> 6, k = tid & 63;

    float Wreg[DIN], wtreg[64];
    #pragma unroll
    for (int d = 0; d < DIN; d++) Wreg[d] = W[d * 64 + k];
    #pragma unroll
    for (int m = 0; m < 64; m++) wtreg[m] = wt[m * 64 + k];
    const float bk = b[k];
    const float* X = Xext ? Xext : g_V;
    const int rowbase = blockIdx.x * 32;

    for (int rb = 0; rb < 8; rb++) {
        int row = rowbase + rb * 4 + g;
        if (k < DIN) sx[g][k] = X[row * DIN + k];
        __syncthreads();
        float h = bk;
        #pragma unroll
        for (int d = 0; d < DIN; d++) h = fmaf(sx[g][d], Wreg[d], h);
        h = fmaxf(h, 0.f);
        sh[g][k] = h;
        __syncthreads();
        float acc = 0.f;
        #pragma unroll
        for (int m = 0; m < 64; m++) acc = fmaf(sh[g][m], wtreg[m], acc);
        g_G[row * 64 + k] = acc;
        sgt[rb * 4 + g][k] = __float2half(acc);
    }
    __syncthreads();
    // coalesced transposed store: g_GT[k][rowbase..rowbase+31]
    const int kk = tid >> 2, seg = tid & 3;
    __half tmp[8];
    #pragma unroll
    for (int r = 0; r < 8; r++) tmp[r] = sgt[seg * 8 + r][kk];
    *(float4*)(g_GT + kk * NN + rowbase + seg * 8) = *(float4*)tmp;
}

// ============================================================
// weight: w = exp(exp(-alpha*dR2)) with pre-scaled coords.
// u = 2^(-(de^2+dp^2)),  w = 2^(u*log2e)
// ============================================================
__device__ __forceinline__ float wfun(float ei, float pii, float ex, float px, float tps) {
    const float LOG2E = 1.44269504088896340736f;
    float de = ei - ex;
    float dp = fabsf(pii - px);
    dp = fminf(dp, tps - dp);
    float drn = fmaf(de, -de, -dp * dp);
    float u; asm("ex2.approx.f32 %0, %1;" : "=f"(u) : "f"(drn));
    float w; asm("ex2.approx.f32 %0, %1;" : "=f"(w) : "f"(u * LOG2E));
    return w;
}

__device__ __forceinline__ uint32_t packh2(float a, float b) {
    __half2 h = __floats2half2_rn(a, b);
    return *(uint32_t*)&h;
}

// ============================================================
// pass: S@G on HMMA (mma.sync m16n8k16). A-fragment (weights) generated
// in registers on the fly; B = G^T tile via ldmatrix; fp32 denominator.
// ============================================================
__global__ __launch_bounds__(256, 2) void pass_kernel(const float* __restrict__ alpha)
{
    __shared__ __half sG[64 * SGS];   // [feature][j] padded
    __shared__ float2 sEP[JT];

    const int tid = threadIdx.x;
    const int warp = tid >> 5, lane = tid & 31;
    const int gid = lane >> 2, tig = lane & 3;
    const int rowtile = blockIdx.x, jsplit = blockIdx.y;
    const int j0base = jsplit * JSPAN;

    const float LOG2E = 1.44269504088896340736f;
    const float TWOPI = 6.28318530717958647692f;
    const float tps = TWOPI * sqrtf(alpha[0] * LOG2E);   // scaled 2*pi

    const int row0 = rowtile * MT + warp * 16 + gid;
    const float2 e0 = g_ep[row0];
    const float2 e1 = g_ep[row0 + 8];

    // ldmatrix per-lane address offset (halves): matrices (nt,kh) pairs
    const int m = lane >> 3;
    const int bro = ((m >> 1) * 8 + (lane & 7)) * SGS + (m & 1) * 8;

    uint32_t sgb;
    asm("{ .reg .u64 t; cvta.to.shared.u64 t, %1; cvt.u32.u64 %0, t; }" : "=r"(sgb) : "l"(sG));

    float acc[8][4];
    #pragma unroll
    for (int nt = 0; nt < 8; nt++)
        #pragma unroll
        for (int q = 0; q < 4; q++) acc[nt][q] = 0.f;
    float d0 = 0.f, d1 = 0.f;

    for (int t = 0; t < NTILE; t++) {
        const int j0 = j0base + t * JT;
        __syncthreads();
        // load G tile: 64 x 128 halves
        #pragma unroll
        for (int i = 0; i < 4; i++) {
            int idx = tid + i * 256;
            int f = idx >> 4, c = idx & 15;
            *(float4*)(sG + f * SGS + c * 8) = *(const float4*)(g_GT + f * NN + j0 + c * 8);
        }
        if (tid < 64)
            ((float4*)sEP)[tid] = ((const float4*)((const float*)g_ep + j0 * 2))[tid];
        __syncthreads();

        #pragma unroll
        for (int ks = 0; ks < 8; ks++) {
            const int jj = ks * 16;
            // ---- A fragment: 8 weights in mma layout ----
            float4 p0 = *(const float4*)(&sEP[jj + tig * 2]);       // k-half 0: j, j+1
            float4 p1 = *(const float4*)(&sEP[jj + 8 + tig * 2]);   // k-half 1
            float w00 = wfun(e0.x, e0.y, p0.x, p0.y, tps);
            float w01 = wfun(e0.x, e0.y, p0.z, p0.w, tps);
            float w10 = wfun(e1.x, e1.y, p0.x, p0.y, tps);
            float w11 = wfun(e1.x, e1.y, p0.z, p0.w, tps);
            float w02 = wfun(e0.x, e0.y, p1.x, p1.y, tps);
            float w03 = wfun(e0.x, e0.y, p1.z, p1.w, tps);
            float w12 = wfun(e1.x, e1.y, p1.x, p1.y, tps);
            float w13 = wfun(e1.x, e1.y, p1.z, p1.w, tps);
            d0 += (w00 + w01) + (w02 + w03);
            d1 += (w10 + w11) + (w12 + w13);
            uint32_t af0 = packh2(w00, w01);
            uint32_t af1 = packh2(w10, w11);
            uint32_t af2 = packh2(w02, w03);
            uint32_t af3 = packh2(w12, w13);

            // ---- B fragments via ldmatrix.x4 (2 n-tiles each) ----
            uint32_t bf[8][2];
            #pragma unroll
            for (int q = 0; q < 4; q++) {
                uint32_t addr = sgb + (uint32_t)(q * 16 * SGS + bro + jj) * 2u;
                asm volatile("ldmatrix.sync.aligned.m8n8.x4.shared.b16 {%0,%1,%2,%3}, [%4];"
                    : "=r"(bf[2 * q][0]), "=r"(bf[2 * q][1]),
                      "=r"(bf[2 * q + 1][0]), "=r"(bf[2 * q + 1][1])
                    : "r"(addr));
            }
            // ---- MMAs ----
            #pragma unroll
            for (int nt = 0; nt < 8; nt++) {
                asm volatile(
                    "mma.sync.aligned.m16n8k16.row.col.f32.f16.f16.f32 "
                    "{%0,%1,%2,%3}, {%4,%5,%6,%7}, {%8,%9}, {%0,%1,%2,%3};"
                    : "+f"(acc[nt][0]), "+f"(acc[nt][1]), "+f"(acc[nt][2]), "+f"(acc[nt][3])
                    : "r"(af0), "r"(af1), "r"(af2), "r"(af3),
                      "r"(bf[nt][0]), "r"(bf[nt][1]));
            }
        }
    }

    // denominator: reduce over the 4 lanes of the tig group
    d0 += __shfl_xor_sync(0xffffffffu, d0, 1);
    d0 += __shfl_xor_sync(0xffffffffu, d0, 2);
    d1 += __shfl_xor_sync(0xffffffffu, d1, 1);
    d1 += __shfl_xor_sync(0xffffffffu, d1, 2);

    float* np = g_num + (size_t)jsplit * NN * DD;
    #pragma unroll
    for (int nt = 0; nt < 8; nt++) {
        *(float2*)(np + (size_t)row0 * DD + nt * 8 + tig * 2) =
            make_float2(acc[nt][0], acc[nt][1]);
        *(float2*)(np + (size_t)(row0 + 8) * DD + nt * 8 + tig * 2) =
            make_float2(acc[nt][2], acc[nt][3]);
    }
    if (tig == 0) {
        g_den[jsplit * NN + row0] = d0;
        g_den[jsplit * NN + row0 + 8] = d1;
    }
}

// ============================================================
// finalize: V = relu(num/den + G + bs)
// ============================================================
__global__ __launch_bounds__(256) void finalize_kernel(const float* __restrict__ bs)
{
    int gid = blockIdx.x * 256 + threadIdx.x;
    int i = gid >> 6;
    float ds = 0.f, ns = 0.f;
    #pragma unroll
    for (int s = 0; s < NSPLIT; s++) {
        ds += g_den[s * NN + i];
        ns += g_num[(size_t)s * NN * DD + gid];
    }
    float v = ns / ds + g_G[gid] + bs[0];
    g_V[gid] = fmaxf(v, 0.f);
}

// ============================================================
// reduce + head
// ============================================================
__global__ __launch_bounds__(256) void reduce_kernel()
{
    __shared__ float s[4][64];
    int tid = threadIdx.x;
    int k = tid & 63;
    int rg = tid >> 6;
    int bkt = blockIdx.x;
    float acc = 0.f;
    for (int r = rg; r < 128; r += 4)
        acc += g_V[(bkt * 128 + r) * 64 + k];
    s[rg][k] = acc;
    __syncthreads();
    if (tid < 64)
        g_part[bkt * 64 + tid] = s[0][tid] + s[1][tid] + s[2][tid] + s[3][tid];
}

__global__ void head_kernel(const float* __restrict__ Wl,
                            const float* __restrict__ bl,
                            float* __restrict__ out)
{
    __shared__ float sv[64];
    int t = threadIdx.x;
    float sk = 0.f;
    for (int b = 0; b < 64; b++) sk += g_part[b * 64 + t];
    sv[t] = sk * Wl[t];
    __syncthreads();
    if (t == 0) {
        float s = 0.f;
        for (int i = 0; i < 64; i++) s += sv[i];
        s += bl[0];
        out[0] = 1.f / (1.f + expf(-s));
    }
}

extern "C" void kernel_launch(void* const* d_in, const int* in_sizes, int n_in,
                              void* d_out, int out_size)
{
    const float* x     = (const float*)d_in[0];
    const float* alpha = (const float*)d_in[1];
    const float* W1    = (const float*)d_in[2];
    const float* b1    = (const float*)d_in[3];
    const float* wt1   = (const float*)d_in[4];
    const float* bs1   = (const float*)d_in[5];
    const float* W2    = (const float*)d_in[6];
    const float* b2    = (const float*)d_in[7];
    const float* wt2   = (const float*)d_in[8];
    const float* bs2   = (const float*)d_in[9];
    const float* Wl    = (const float*)d_in[10];
    const float* bl    = (const float*)d_in[11];
    float* out = (float*)d_out;

    dim3 pg(NN / MT, NSPLIT);

    ep_kernel<<<NN / 256, 256>>>(x, alpha);
    // layer 1
    prep_kernel<7><<<NN / 32, 256>>>(x, W1, b1, wt1);
    pass_kernel<<<pg, 256>>>(alpha);
    finalize_kernel<<<NN * DD / 256, 256>>>(bs1);
    // layer 2
    prep_kernel<64><<<NN / 32, 256>>>(nullptr, W2, b2, wt2);
    pass_kernel<<<pg, 256>>>(alpha);
    finalize_kernel<<<NN * DD / 256, 256>>>(bs2);
    // head
    reduce_kernel<<<64, 256>>>();
    head_kernel<<<1, 64>>>(Wl, bl, out);
}

// round 5
// speedup vs baseline: 4.9403x; 1.0677x over previous
#include <cuda_runtime.h>
#include <cuda_fp16.h>
#include <math.h>
#include <stdint.h>

#define NN 8192
#define DD 64
#define NSPLIT 4
#define MT 128          // rows per CTA
#define JT 128          // j tile
#define JSPAN (NN / NSPLIT)        // 2048 j's per CTA
#define NTILE (JSPAN / JT)         // 16 j-tiles per CTA
#define SGS 136         // padded sG row stride (halves)

// ---- static device scratch (no allocation allowed) ----
__device__ float  g_G[NN * DD];            // G = relu(X@W+b)@wt (fp32, row-major)
__device__ __half g_GT[DD * NN];           // G transposed, fp16 (feature-major)
__device__ float  g_V[NN * DD];            // layer output
__device__ float  g_num[NSPLIT * NN * DD]; // numerator partials
__device__ float  g_den[NSPLIT * NN];      // denominator partials (written by pass1 only)
__device__ float2 g_ep[NN];                // scaled (eta*s, phi*s)
__device__ float  g_part[64 * 64];
// weight-fragment cache: identical S for both layers. 8.4M uint4 = 134MB.
__device__ uint4  g_wc[64 * 8 * NSPLIT * NTILE * 8 * 32];

// ============================================================
// ep: pack (eta, phi), pre-scaled by s = sqrt(alpha * log2(e))
// ============================================================
__global__ void ep_kernel(const float* __restrict__ x, const float* __restrict__ alpha) {
    const float LOG2E = 1.44269504088896340736f;
    float s = sqrtf(alpha[0] * LOG2E);
    int j = blockIdx.x * 256 + threadIdx.x;
    g_ep[j] = make_float2(x[j * 7 + 1] * s, x[j * 7 + 2] * s);
}

// ============================================================
// prep: G = relu(X@W+b)@wt with W/wt columns in registers.
// ============================================================
template<int DIN>
__global__ __launch_bounds__(256) void prep_kernel(
    const float* __restrict__ Xext, const float* __restrict__ W,
    const float* __restrict__ b, const float* __restrict__ wt)
{
    __shared__ float sx[4][(DIN <= 8) ? 8 : 64];
    __shared__ float sh[4][64];
    __shared__ __half sgt[32][64];

    const int tid = threadIdx.x;
    const int g = tid >> 6, k = tid & 63;

    float Wreg[DIN], wtreg[64];
    #pragma unroll
    for (int d = 0; d < DIN; d++) Wreg[d] = W[d * 64 + k];
    #pragma unroll
    for (int m = 0; m < 64; m++) wtreg[m] = wt[m * 64 + k];
    const float bk = b[k];
    const float* X = Xext ? Xext : g_V;
    const int rowbase = blockIdx.x * 32;

    for (int rb = 0; rb < 8; rb++) {
        int row = rowbase + rb * 4 + g;
        if (k < DIN) sx[g][k] = X[row * DIN + k];
        __syncthreads();
        float h = bk;
        #pragma unroll
        for (int d = 0; d < DIN; d++) h = fmaf(sx[g][d], Wreg[d], h);
        h = fmaxf(h, 0.f);
        sh[g][k] = h;
        __syncthreads();
        float acc = 0.f;
        #pragma unroll
        for (int m = 0; m < 64; m++) acc = fmaf(sh[g][m], wtreg[m], acc);
        g_G[row * 64 + k] = acc;
        sgt[rb * 4 + g][k] = __float2half(acc);
    }
    __syncthreads();
    const int kk = tid >> 2, seg = tid & 3;
    __half tmp[8];
    #pragma unroll
    for (int r = 0; r < 8; r++) tmp[r] = sgt[seg * 8 + r][kk];
    *(float4*)(g_GT + kk * NN + rowbase + seg * 8) = *(float4*)tmp;
}

// ============================================================
// weight: w = exp(exp(-alpha*dR2)) with pre-scaled coords.
// ============================================================
__device__ __forceinline__ float wfun(float ei, float pii, float ex, float px, float tps) {
    const float LOG2E = 1.44269504088896340736f;
    float de = ei - ex;
    float dp = fabsf(pii - px);
    dp = fminf(dp, tps - dp);
    float drn = fmaf(de, -de, -dp * dp);
    float u; asm("ex2.approx.f32 %0, %1;" : "=f"(u) : "f"(drn));
    float w; asm("ex2.approx.f32 %0, %1;" : "=f"(w) : "f"(u * LOG2E));
    return w;
}

__device__ __forceinline__ uint32_t packh2(float a, float b) {
    __half2 h = __floats2half2_rn(a, b);
    return *(uint32_t*)&h;
}

// ============================================================
// pass: S@G on HMMA. GEN=1: compute weights, cache fragments + den.
//       GEN=0: load cached fragments (1 LDG.128/ks), skip wgen/den.
// ============================================================
template<int GEN>
__global__ __launch_bounds__(256, 2) void pass_kernel(const float* __restrict__ alpha)
{
    __shared__ __half sG[64 * SGS];   // [feature][j] padded
    __shared__ float2 sEP[JT];

    const int tid = threadIdx.x;
    const int warp = tid >> 5, lane = tid & 31;
    const int gid = lane >> 2, tig = lane & 3;
    const int rowtile = blockIdx.x, jsplit = blockIdx.y;
    const int j0base = jsplit * JSPAN;

    const int row0 = rowtile * MT + warp * 16 + gid;

    float tps = 0.f, e0x = 0.f, e0y = 0.f, e1x = 0.f, e1y = 0.f;
    if (GEN) {
        const float LOG2E = 1.44269504088896340736f;
        const float TWOPI = 6.28318530717958647692f;
        tps = TWOPI * sqrtf(alpha[0] * LOG2E);
        float2 e0 = g_ep[row0]; e0x = e0.x; e0y = e0.y;
        float2 e1 = g_ep[row0 + 8]; e1x = e1.x; e1y = e1.y;
    }

    // weight-cache base for this (rowtile, warp, jsplit), lane-major
    uint4* wcp = g_wc + ((((size_t)rowtile * 8 + warp) * NSPLIT + jsplit) * (NTILE * 8) + 0) * 32 + lane;

    // ldmatrix per-lane address offset (halves)
    const int m = lane >> 3;
    const int bro = ((m >> 1) * 8 + (lane & 7)) * SGS + (m & 1) * 8;

    uint32_t sgb;
    asm("{ .reg .u64 t; cvta.to.shared.u64 t, %1; cvt.u32.u64 %0, t; }" : "=r"(sgb) : "l"(sG));

    float acc[8][4];
    #pragma unroll
    for (int nt = 0; nt < 8; nt++)
        #pragma unroll
        for (int q = 0; q < 4; q++) acc[nt][q] = 0.f;
    float d0 = 0.f, d1 = 0.f;

    for (int t = 0; t < NTILE; t++) {
        const int j0 = j0base + t * JT;
        __syncthreads();
        #pragma unroll
        for (int i = 0; i < 4; i++) {
            int idx = tid + i * 256;
            int f = idx >> 4, c = idx & 15;
            *(float4*)(sG + f * SGS + c * 8) = *(const float4*)(g_GT + f * NN + j0 + c * 8);
        }
        if (GEN && tid < 64)
            ((float4*)sEP)[tid] = ((const float4*)((const float*)g_ep + j0 * 2))[tid];
        __syncthreads();

        uint4 wf[8];
        if (!GEN) {
            // front-batched fragment loads: MLP=8 hides DRAM latency
            #pragma unroll
            for (int ks = 0; ks < 8; ks++)
                wf[ks] = wcp[(t * 8 + ks) * 32];
        }

        #pragma unroll
        for (int ks = 0; ks < 8; ks++) {
            const int jj = ks * 16;
            uint32_t af0, af1, af2, af3;
            if (GEN) {
                float4 p0 = *(const float4*)(&sEP[jj + tig * 2]);
                float4 p1 = *(const float4*)(&sEP[jj + 8 + tig * 2]);
                float w00 = wfun(e0x, e0y, p0.x, p0.y, tps);
                float w01 = wfun(e0x, e0y, p0.z, p0.w, tps);
                float w10 = wfun(e1x, e1y, p0.x, p0.y, tps);
                float w11 = wfun(e1x, e1y, p0.z, p0.w, tps);
                float w02 = wfun(e0x, e0y, p1.x, p1.y, tps);
                float w03 = wfun(e0x, e0y, p1.z, p1.w, tps);
                float w12 = wfun(e1x, e1y, p1.x, p1.y, tps);
                float w13 = wfun(e1x, e1y, p1.z, p1.w, tps);
                d0 += (w00 + w01) + (w02 + w03);
                d1 += (w10 + w11) + (w12 + w13);
                af0 = packh2(w00, w01);
                af1 = packh2(w10, w11);
                af2 = packh2(w02, w03);
                af3 = packh2(w12, w13);
                wcp[(t * 8 + ks) * 32] = make_uint4(af0, af1, af2, af3);
            } else {
                af0 = wf[ks].x; af1 = wf[ks].y; af2 = wf[ks].z; af3 = wf[ks].w;
            }

            // two half-groups of (2 ldmatrix.x4 + 4 MMA) to cap live regs
            #pragma unroll
            for (int h = 0; h < 2; h++) {
                uint32_t bf[4][2];
                #pragma unroll
                for (int q = 0; q < 2; q++) {
                    uint32_t addr = sgb + (uint32_t)((h * 2 + q) * 16 * SGS + bro + jj) * 2u;
                    asm volatile("ldmatrix.sync.aligned.m8n8.x4.shared.b16 {%0,%1,%2,%3}, [%4];"
                        : "=r"(bf[2 * q][0]), "=r"(bf[2 * q][1]),
                          "=r"(bf[2 * q + 1][0]), "=r"(bf[2 * q + 1][1])
                        : "r"(addr));
                }
                #pragma unroll
                for (int nt = 0; nt < 4; nt++) {
                    asm volatile(
                        "mma.sync.aligned.m16n8k16.row.col.f32.f16.f16.f32 "
                        "{%0,%1,%2,%3}, {%4,%5,%6,%7}, {%8,%9}, {%0,%1,%2,%3};"
                        : "+f"(acc[h * 4 + nt][0]), "+f"(acc[h * 4 + nt][1]),
                          "+f"(acc[h * 4 + nt][2]), "+f"(acc[h * 4 + nt][3])
                        : "r"(af0), "r"(af1), "r"(af2), "r"(af3),
                          "r"(bf[nt][0]), "r"(bf[nt][1]));
                }
            }
        }
    }

    if (GEN) {
        d0 += __shfl_xor_sync(0xffffffffu, d0, 1);
        d0 += __shfl_xor_sync(0xffffffffu, d0, 2);
        d1 += __shfl_xor_sync(0xffffffffu, d1, 1);
        d1 += __shfl_xor_sync(0xffffffffu, d1, 2);
        if (tig == 0) {
            g_den[jsplit * NN + row0] = d0;
            g_den[jsplit * NN + row0 + 8] = d1;
        }
    }

    float* np = g_num + (size_t)jsplit * NN * DD;
    #pragma unroll
    for (int nt = 0; nt < 8; nt++) {
        *(float2*)(np + (size_t)row0 * DD + nt * 8 + tig * 2) =
            make_float2(acc[nt][0], acc[nt][1]);
        *(float2*)(np + (size_t)(row0 + 8) * DD + nt * 8 + tig * 2) =
            make_float2(acc[nt][2], acc[nt][3]);
    }
}

// ============================================================
// finalize: V = relu(num/den + G + bs)
// ============================================================
__global__ __launch_bounds__(256) void finalize_kernel(const float* __restrict__ bs)
{
    int gid = blockIdx.x * 256 + threadIdx.x;
    int i = gid >> 6;
    float ds = 0.f, ns = 0.f;
    #pragma unroll
    for (int s = 0; s < NSPLIT; s++) {
        ds += g_den[s * NN + i];
        ns += g_num[(size_t)s * NN * DD + gid];
    }
    float v = ns / ds + g_G[gid] + bs[0];
    g_V[gid] = fmaxf(v, 0.f);
}

// ============================================================
// reduce + head
// ============================================================
__global__ __launch_bounds__(256) void reduce_kernel()
{
    __shared__ float s[4][64];
    int tid = threadIdx.x;
    int k = tid & 63;
    int rg = tid >> 6;
    int bkt = blockIdx.x;
    float acc = 0.f;
    for (int r = rg; r < 128; r += 4)
        acc += g_V[(bkt * 128 + r) * 64 + k];
    s[rg][k] = acc;
    __syncthreads();
    if (tid < 64)
        g_part[bkt * 64 + tid] = s[0][tid] + s[1][tid] + s[2][tid] + s[3][tid];
}

__global__ void head_kernel(const float* __restrict__ Wl,
                            const float* __restrict__ bl,
                            float* __restrict__ out)
{
    __shared__ float sv[64];
    int t = threadIdx.x;
    float sk = 0.f;
    for (int b = 0; b < 64; b++) sk += g_part[b * 64 + t];
    sv[t] = sk * Wl[t];
    __syncthreads();
    if (t == 0) {
        float s = 0.f;
        for (int i = 0; i < 64; i++) s += sv[i];
        s += bl[0];
        out[0] = 1.f / (1.f + expf(-s));
    }
}

extern "C" void kernel_launch(void* const* d_in, const int* in_sizes, int n_in,
                              void* d_out, int out_size)
{
    const float* x     = (const float*)d_in[0];
    const float* alpha = (const float*)d_in[1];
    const float* W1    = (const float*)d_in[2];
    const float* b1    = (const float*)d_in[3];
    const float* wt1   = (const float*)d_in[4];
    const float* bs1   = (const float*)d_in[5];
    const float* W2    = (const float*)d_in[6];
    const float* b2    = (const float*)d_in[7];
    const float* wt2   = (const float*)d_in[8];
    const float* bs2   = (const float*)d_in[9];
    const float* Wl    = (const float*)d_in[10];
    const float* bl    = (const float*)d_in[11];
    float* out = (float*)d_out;

    dim3 pg(NN / MT, NSPLIT);

    ep_kernel<<<NN / 256, 256>>>(x, alpha);
    // layer 1: generate + cache weight fragments
    prep_kernel<7><<<NN / 32, 256>>>(x, W1, b1, wt1);
    pass_kernel<1><<<pg, 256>>>(alpha);
    finalize_kernel<<<NN * DD / 256, 256>>>(bs1);
    // layer 2: replay cached fragments (den reused from layer 1)
    prep_kernel<64><<<NN / 32, 256>>>(nullptr, W2, b2, wt2);
    pass_kernel<0><<<pg, 256>>>(alpha);
    finalize_kernel<<<NN * DD / 256, 256>>>(bs2);
    // head
    reduce_kernel<<<64, 256>>>();
    head_kernel<<<1, 64>>>(Wl, bl, out);
}

// round 6
// speedup vs baseline: 5.3088x; 1.0746x over previous
#include <cuda_runtime.h>
#include <cuda_fp16.h>
#include <math.h>
#include <stdint.h>

#define NN 8192
#define DD 64
#define NSPLIT 4
#define MT 128          // rows per CTA
#define JT 128          // j tile
#define JSPAN (NN / NSPLIT)        // 2048 j's per CTA
#define NTILE (JSPAN / JT)         // 16 j-tiles per CTA
#define SGS 136         // padded sG row stride (halves)

// ---- static device scratch (no allocation allowed) ----
__device__ float  g_G[NN * DD];            // G = relu(X@W+b)@wt (fp32, row-major)
__device__ __half g_GT[DD * NN];           // G transposed, fp16 (feature-major)
__device__ float  g_V[NN * DD];            // layer output
__device__ float  g_num[NSPLIT * NN * DD]; // numerator partials
__device__ float  g_den[NSPLIT * NN];      // denominator partials (pass1 only)
__device__ float2 g_ep[NN];                // scaled (eta*s, phi*s)
__device__ float  g_part[64 * 64];
// weight-fragment cache: identical S for both layers. 8.4M uint4 = 134MB.
__device__ uint4  g_wc[64 * 8 * NSPLIT * NTILE * 8 * 32];

// ============================================================
// ep: pack (eta, phi), pre-scaled by s = sqrt(alpha * log2(e))
// ============================================================
__global__ void ep_kernel(const float* __restrict__ x, const float* __restrict__ alpha) {
    const float LOG2E = 1.44269504088896340736f;
    float s = sqrtf(alpha[0] * LOG2E);
    int j = blockIdx.x * 256 + threadIdx.x;
    g_ep[j] = make_float2(x[j * 7 + 1] * s, x[j * 7 + 2] * s);
}

// ============================================================
// prep: G = relu(X@W+b)@wt with W/wt columns in registers.
// ============================================================
template<int DIN>
__global__ __launch_bounds__(256) void prep_kernel(
    const float* __restrict__ Xext, const float* __restrict__ W,
    const float* __restrict__ b, const float* __restrict__ wt)
{
    __shared__ float sx[4][(DIN <= 8) ? 8 : 64];
    __shared__ float sh[4][64];
    __shared__ __half sgt[32][64];

    const int tid = threadIdx.x;
    const int g = tid >> 6, k = tid & 63;

    float Wreg[DIN], wtreg[64];
    #pragma unroll
    for (int d = 0; d < DIN; d++) Wreg[d] = W[d * 64 + k];
    #pragma unroll
    for (int m = 0; m < 64; m++) wtreg[m] = wt[m * 64 + k];
    const float bk = b[k];
    const float* X = Xext ? Xext : g_V;
    const int rowbase = blockIdx.x * 32;

    for (int rb = 0; rb < 8; rb++) {
        int row = rowbase + rb * 4 + g;
        if (k < DIN) sx[g][k] = X[row * DIN + k];
        __syncthreads();
        float h = bk;
        #pragma unroll
        for (int d = 0; d < DIN; d++) h = fmaf(sx[g][d], Wreg[d], h);
        h = fmaxf(h, 0.f);
        sh[g][k] = h;
        __syncthreads();
        float acc = 0.f;
        #pragma unroll
        for (int m = 0; m < 64; m++) acc = fmaf(sh[g][m], wtreg[m], acc);
        g_G[row * 64 + k] = acc;
        sgt[rb * 4 + g][k] = __float2half(acc);
    }
    __syncthreads();
    const int kk = tid >> 2, seg = tid & 3;
    __half tmp[8];
    #pragma unroll
    for (int r = 0; r < 8; r++) tmp[r] = sgt[seg * 8 + r][kk];
    *(float4*)(g_GT + kk * NN + rowbase + seg * 8) = *(float4*)tmp;
}

// ============================================================
// drn = log2(log2e) - alpha*log2e*dR^2  (coords pre-scaled), so that
// w = exp(exp(-alpha dR^2)) = 2^(2^drn)
// ============================================================
__device__ __forceinline__ float drnfun(float ei, float pii, float ex, float px, float tps) {
    const float LL = 0.52876637294489770f;   // log2(log2(e))
    float de = ei - ex;
    float d  = pii - px;
    float ad = fabsf(d);
    float dp = fminf(ad, tps - ad);
    return fmaf(de, -de, fmaf(dp, -dp, LL));
}

// pack two drn -> half2 weights {lo=w0, hi=w1} via two packed ex2
__device__ __forceinline__ uint32_t wpair(float drn0, float drn1) {
    uint32_t r;
    asm("{\n\t.reg .b32 t;\n\t"
        "cvt.rn.f16x2.f32 t, %2, %1;\n\t"
        "ex2.approx.f16x2 t, t;\n\t"
        "ex2.approx.f16x2 %0, t;\n\t}"
        : "=r"(r) : "f"(drn0), "f"(drn1));
    return r;
}

// ============================================================
// pass: S@G on HMMA. GEN=1: compute weights (packed ex2), cache
// fragments, den via extra MMA against constant ones-B.
// GEN=0: replay cached fragments, skip weight math and den.
// ============================================================
template<int GEN>
__global__ __launch_bounds__(256, 2) void pass_kernel(const float* __restrict__ alpha)
{
    __shared__ __half sG[64 * SGS];   // [feature][j] padded
    __shared__ float2 sEP[JT];

    const int tid = threadIdx.x;
    const int warp = tid >> 5, lane = tid & 31;
    const int gid = lane >> 2, tig = lane & 3;
    const int rowtile = blockIdx.x, jsplit = blockIdx.y;
    const int j0base = jsplit * JSPAN;

    const int row0 = rowtile * MT + warp * 16 + gid;

    float tps = 0.f, e0x = 0.f, e0y = 0.f, e1x = 0.f, e1y = 0.f;
    if (GEN) {
        const float LOG2E = 1.44269504088896340736f;
        const float TWOPI = 6.28318530717958647692f;
        tps = TWOPI * sqrtf(alpha[0] * LOG2E);
        float2 e0 = g_ep[row0]; e0x = e0.x; e0y = e0.y;
        float2 e1 = g_ep[row0 + 8]; e1x = e1.x; e1y = e1.y;
    }

    // weight-cache base for this (rowtile, warp, jsplit), lane-major
    uint4* wcp = g_wc + ((((size_t)rowtile * 8 + warp) * NSPLIT + jsplit) * (NTILE * 8)) * 32 + lane;

    // ldmatrix per-lane address offset (halves)
    const int m = lane >> 3;
    const int bro = ((m >> 1) * 8 + (lane & 7)) * SGS + (m & 1) * 8;

    uint32_t sgb;
    asm("{ .reg .u64 t; cvta.to.shared.u64 t, %1; cvt.u32.u64 %0, t; }" : "=r"(sgb) : "l"(sG));

    float acc[8][4];
    #pragma unroll
    for (int nt = 0; nt < 8; nt++)
        #pragma unroll
        for (int q = 0; q < 4; q++) acc[nt][q] = 0.f;
    float accd[4] = {0.f, 0.f, 0.f, 0.f};   // den accumulator (GEN only)

    for (int t = 0; t < NTILE; t++) {
        const int j0 = j0base + t * JT;
        __syncthreads();
        #pragma unroll
        for (int i = 0; i < 4; i++) {
            int idx = tid + i * 256;
            int f = idx >> 4, c = idx & 15;
            *(float4*)(sG + f * SGS + c * 8) = *(const float4*)(g_GT + f * NN + j0 + c * 8);
        }
        if (GEN && tid < 64)
            ((float4*)sEP)[tid] = ((const float4*)((const float*)g_ep + j0 * 2))[tid];
        __syncthreads();

        uint4 wf[8];
        if (!GEN) {
            #pragma unroll
            for (int ks = 0; ks < 8; ks++)
                wf[ks] = wcp[(t * 8 + ks) * 32];
        }

        #pragma unroll
        for (int ks = 0; ks < 8; ks++) {
            const int jj = ks * 16;
            uint32_t af0, af1, af2, af3;
            if (GEN) {
                float4 p0 = *(const float4*)(&sEP[jj + tig * 2]);
                float4 p1 = *(const float4*)(&sEP[jj + 8 + tig * 2]);
                float dn00 = drnfun(e0x, e0y, p0.x, p0.y, tps);
                float dn01 = drnfun(e0x, e0y, p0.z, p0.w, tps);
                float dn10 = drnfun(e1x, e1y, p0.x, p0.y, tps);
                float dn11 = drnfun(e1x, e1y, p0.z, p0.w, tps);
                float dn02 = drnfun(e0x, e0y, p1.x, p1.y, tps);
                float dn03 = drnfun(e0x, e0y, p1.z, p1.w, tps);
                float dn12 = drnfun(e1x, e1y, p1.x, p1.y, tps);
                float dn13 = drnfun(e1x, e1y, p1.z, p1.w, tps);
                af0 = wpair(dn00, dn01);
                af1 = wpair(dn10, dn11);
                af2 = wpair(dn02, dn03);
                af3 = wpair(dn12, dn13);
                wcp[(t * 8 + ks) * 32] = make_uint4(af0, af1, af2, af3);
                // den: MMA against constant all-ones B fragment
                asm volatile(
                    "mma.sync.aligned.m16n8k16.row.col.f32.f16.f16.f32 "
                    "{%0,%1,%2,%3}, {%4,%5,%6,%7}, {%8,%8}, {%0,%1,%2,%3};"
                    : "+f"(accd[0]), "+f"(accd[1]), "+f"(accd[2]), "+f"(accd[3])
                    : "r"(af0), "r"(af1), "r"(af2), "r"(af3), "r"(0x3C003C00u));
            } else {
                af0 = wf[ks].x; af1 = wf[ks].y; af2 = wf[ks].z; af3 = wf[ks].w;
            }

            // two half-groups of (2 ldmatrix.x4 + 4 MMA) to cap live regs
            #pragma unroll
            for (int h = 0; h < 2; h++) {
                uint32_t bf[4][2];
                #pragma unroll
                for (int q = 0; q < 2; q++) {
                    uint32_t addr = sgb + (uint32_t)((h * 2 + q) * 16 * SGS + bro + jj) * 2u;
                    asm volatile("ldmatrix.sync.aligned.m8n8.x4.shared.b16 {%0,%1,%2,%3}, [%4];"
                        : "=r"(bf[2 * q][0]), "=r"(bf[2 * q][1]),
                          "=r"(bf[2 * q + 1][0]), "=r"(bf[2 * q + 1][1])
                        : "r"(addr));
                }
                #pragma unroll
                for (int nt = 0; nt < 4; nt++) {
                    asm volatile(
                        "mma.sync.aligned.m16n8k16.row.col.f32.f16.f16.f32 "
                        "{%0,%1,%2,%3}, {%4,%5,%6,%7}, {%8,%9}, {%0,%1,%2,%3};"
                        : "+f"(acc[h * 4 + nt][0]), "+f"(acc[h * 4 + nt][1]),
                          "+f"(acc[h * 4 + nt][2]), "+f"(acc[h * 4 + nt][3])
                        : "r"(af0), "r"(af1), "r"(af2), "r"(af3),
                          "r"(bf[nt][0]), "r"(bf[nt][1]));
                }
            }
        }
    }

    if (GEN && tig == 0) {
        g_den[jsplit * NN + row0] = accd[0];
        g_den[jsplit * NN + row0 + 8] = accd[2];
    }

    float* np = g_num + (size_t)jsplit * NN * DD;
    #pragma unroll
    for (int nt = 0; nt < 8; nt++) {
        *(float2*)(np + (size_t)row0 * DD + nt * 8 + tig * 2) =
            make_float2(acc[nt][0], acc[nt][1]);
        *(float2*)(np + (size_t)(row0 + 8) * DD + nt * 8 + tig * 2) =
            make_float2(acc[nt][2], acc[nt][3]);
    }
}

// ============================================================
// finalize: V = relu(num/den + G + bs)
// ============================================================
__global__ __launch_bounds__(256) void finalize_kernel(const float* __restrict__ bs)
{
    int gid = blockIdx.x * 256 + threadIdx.x;
    int i = gid >> 6;
    float ds = 0.f, ns = 0.f;
    #pragma unroll
    for (int s = 0; s < NSPLIT; s++) {
        ds += g_den[s * NN + i];
        ns += g_num[(size_t)s * NN * DD + gid];
    }
    float v = ns / ds + g_G[gid] + bs[0];
    g_V[gid] = fmaxf(v, 0.f);
}

// ============================================================
// reduce + head
// ============================================================
__global__ __launch_bounds__(256) void reduce_kernel()
{
    __shared__ float s[4][64];
    int tid = threadIdx.x;
    int k = tid & 63;
    int rg = tid >> 6;
    int bkt = blockIdx.x;
    float acc = 0.f;
    for (int r = rg; r < 128; r += 4)
        acc += g_V[(bkt * 128 + r) * 64 + k];
    s[rg][k] = acc;
    __syncthreads();
    if (tid < 64)
        g_part[bkt * 64 + tid] = s[0][tid] + s[1][tid] + s[2][tid] + s[3][tid];
}

__global__ void head_kernel(const float* __restrict__ Wl,
                            const float* __restrict__ bl,
                            float* __restrict__ out)
{
    __shared__ float sv[64];
    int t = threadIdx.x;
    float sk = 0.f;
    for (int b = 0; b < 64; b++) sk += g_part[b * 64 + t];
    sv[t] = sk * Wl[t];
    __syncthreads();
    if (t == 0) {
        float s = 0.f;
        for (int i = 0; i < 64; i++) s += sv[i];
        s += bl[0];
        out[0] = 1.f / (1.f + expf(-s));
    }
}

extern "C" void kernel_launch(void* const* d_in, const int* in_sizes, int n_in,
                              void* d_out, int out_size)
{
    const float* x     = (const float*)d_in[0];
    const float* alpha = (const float*)d_in[1];
    const float* W1    = (const float*)d_in[2];
    const float* b1    = (const float*)d_in[3];
    const float* wt1   = (const float*)d_in[4];
    const float* bs1   = (const float*)d_in[5];
    const float* W2    = (const float*)d_in[6];
    const float* b2    = (const float*)d_in[7];
    const float* wt2   = (const float*)d_in[8];
    const float* bs2   = (const float*)d_in[9];
    const float* Wl    = (const float*)d_in[10];
    const float* bl    = (const float*)d_in[11];
    float* out = (float*)d_out;

    dim3 pg(NN / MT, NSPLIT);

    ep_kernel<<<NN / 256, 256>>>(x, alpha);
    // layer 1: generate + cache weight fragments
    prep_kernel<7><<<NN / 32, 256>>>(x, W1, b1, wt1);
    pass_kernel<1><<<pg, 256>>>(alpha);
    finalize_kernel<<<NN * DD / 256, 256>>>(bs1);
    // layer 2: replay cached fragments (den reused from layer 1)
    prep_kernel<64><<<NN / 32, 256>>>(nullptr, W2, b2, wt2);
    pass_kernel<0><<<pg, 256>>>(alpha);
    finalize_kernel<<<NN * DD / 256, 256>>>(bs2);
    // head
    reduce_kernel<<<64, 256>>>();
    head_kernel<<<1, 64>>>(Wl, bl, out);
}